// round 16
// baseline (speedup 1.0000x reference)
#include <cuda_runtime.h>
#include <cuda_fp16.h>
#include <stdint.h>

#define FEAT 256
#define N_MAXN 50176
#define E_MAXE 1605632

// ---------------- device scratch (static; no allocation allowed) ------------
__device__ __half g_yh[(size_t)N_MAXN * FEAT];   // fp16: xw (UNSCALED)
__device__ __half g_xh[(size_t)N_MAXN * FEAT];   // fp16 copy of x, [m][k]
__device__ __half g_wt[FEAT * FEAT];             // fp16 W transposed, [n][k]
__device__ int   g_deg[N_MAXN];
__device__ float g_dinv[N_MAXN];
__device__ int   g_off[N_MAXN + 1];
__device__ int   g_cursor[N_MAXN];
__device__ int   g_srcs[E_MAXE];
__device__ int   g_bsum[128];
__device__ int   g_bpre[128];
__device__ int   g_is64;

// ---------------------------------------------------------------------------
// One-time fp32 -> fp16 conversions (hoisted out of the GEMM mainloop).
// ---------------------------------------------------------------------------
__global__ void convert_x_kernel(const float* __restrict__ x, int total4) {
    int i = blockIdx.x * blockDim.x + threadIdx.x;
    if (i >= total4) return;
    float4 v = ((const float4*)x)[i];
    __half2 p0 = __floats2half2_rn(v.x, v.y);
    __half2 p1 = __floats2half2_rn(v.z, v.w);
    ((uint2*)g_xh)[i] = make_uint2(*(uint32_t*)&p0, *(uint32_t*)&p1);
}

// convert W (transposed) + zero degrees + dtype probe, one launch.
// Grid is 65536 threads >= N, so degree zeroing is covered.
__global__ void convert_w_init_kernel(const float* __restrict__ W,
                                      const int* __restrict__ e, int N) {
    int i = blockIdx.x * blockDim.x + threadIdx.x;   // 0..65535
    int n = i >> 8, k = i & 255;
    g_wt[n * FEAT + k] = __float2half_rn(W[k * FEAT + n]);
    if (i < N) g_deg[i] = 0;
    if (blockIdx.x == 0) {
        __shared__ int any_nonzero;
        if (threadIdx.x == 0) any_nonzero = 0;
        __syncthreads();
        int local = 0;
        for (int t = threadIdx.x; t < 512; t += blockDim.x)
            if (e[2 * t + 1] != 0) local = 1;
        if (local) atomicExch(&any_nonzero, 1);
        __syncthreads();
        if (threadIdx.x == 0) g_is64 = any_nonzero ? 0 : 1;
    }
}

__device__ __forceinline__ int load_idx(const void* e, long long i, long long E, bool dst) {
    if (g_is64) {
        const long long* p = (const long long*)e;
        return (int)p[(dst ? E : 0) + i];
    } else {
        const int* p = (const int*)e;
        return p[(dst ? E : 0) + i];
    }
}

__global__ void count_deg_kernel(const void* __restrict__ e, int E) {
    int i = blockIdx.x * blockDim.x + threadIdx.x;
    if (i >= E) return;
    atomicAdd(&g_deg[load_idx(e, i, E, true)], 1);
}

// ---------------------------------------------------------------------------
// Three-level scan, shuffle-based
// ---------------------------------------------------------------------------
#define SCB 512

__global__ __launch_bounds__(SCB) void block_sum_kernel(int N) {
    __shared__ int ws[16];
    int t = threadIdx.x;
    int i = blockIdx.x * SCB + t;
    int v = (i < N) ? g_deg[i] : 0;
#pragma unroll
    for (int off = 16; off > 0; off >>= 1)
        v += __shfl_xor_sync(0xFFFFFFFF, v, off);
    if ((t & 31) == 0) ws[t >> 5] = v;
    __syncthreads();
    if (t < 32) {
        int s = (t < 16) ? ws[t] : 0;
#pragma unroll
        for (int off = 8; off > 0; off >>= 1)
            s += __shfl_xor_sync(0xFFFFFFFF, s, off);
        if (t == 0) g_bsum[blockIdx.x] = s;
    }
}

__global__ __launch_bounds__(128) void scan_bsum_kernel(int NB) {
    __shared__ int wsum[4];
    int t = threadIdx.x;
    int lane = t & 31, w = t >> 5;
    int v = (t < NB) ? g_bsum[t] : 0;
    int inc = v;
#pragma unroll
    for (int off = 1; off < 32; off <<= 1) {
        int n = __shfl_up_sync(0xFFFFFFFF, inc, off);
        if (lane >= off) inc += n;
    }
    if (lane == 31) wsum[w] = inc;
    __syncthreads();
    int wpre = 0;
#pragma unroll
    for (int k = 0; k < 4; k++) wpre += (k < w) ? wsum[k] : 0;
    if (t < NB) g_bpre[t] = wpre + inc - v;   // exclusive
}

__global__ __launch_bounds__(SCB) void scan_final_kernel(int N) {
    __shared__ int wsum[16];
    int t = threadIdx.x;
    int lane = t & 31, w = t >> 5;
    int i = blockIdx.x * SCB + t;
    int d = (i < N) ? g_deg[i] : 0;
    int inc = d;
#pragma unroll
    for (int off = 1; off < 32; off <<= 1) {
        int n = __shfl_up_sync(0xFFFFFFFF, inc, off);
        if (lane >= off) inc += n;
    }
    if (lane == 31) wsum[w] = inc;
    __syncthreads();
    if (w == 0) {
        int s = (lane < 16) ? wsum[lane] : 0;
#pragma unroll
        for (int off = 1; off < 16; off <<= 1) {
            int n = __shfl_up_sync(0xFFFFFFFF, s, off);
            if (lane >= off) s += n;
        }
        if (lane < 16) wsum[lane] = s;
    }
    __syncthreads();
    int wpre = (w == 0) ? 0 : wsum[w - 1];
    if (i < N) {
        int excl = g_bpre[blockIdx.x] + wpre + inc - d;
        g_off[i] = excl;
        g_cursor[i] = excl;
        g_dinv[i] = rsqrtf((float)(d + 1));
        if (i == N - 1) g_off[N] = excl + d;
    }
}

__global__ void fill_kernel(const void* __restrict__ e, int E) {
    int i = blockIdx.x * blockDim.x + threadIdx.x;
    if (i >= E) return;
    int s = load_idx(e, i, E, false);
    int d = load_idx(e, i, E, true);
    int pos = atomicAdd(&g_cursor[d], 1);
    g_srcs[pos] = s;
}

// ---------------------------------------------------------------------------
// fp16 tensor GEMM v5: y = x @ W (fp32 accum, fp16 store, unscaled).
// 3-stage cp.async pipeline + ldmatrix. At iter k: wait_group 1 (tile k ready,
// tile k+1 in flight), prefetch tile k+2, compute tile k.
// BM=128, BN=128, BK=32; 8 warps as 4(M) x 2(N), warp tile 32x64.
// ---------------------------------------------------------------------------
#define BM 128
#define BN 128
#define BK 32
#define KPAD 40   // 80-byte rows; LDSM phases hit all 32 banks (20r mod 32)
#define NSTAGE 3

#define MMA_FP16(d, a, b)                                                      \
    asm volatile(                                                              \
        "mma.sync.aligned.m16n8k16.row.col.f32.f16.f16.f32 "                   \
        "{%0,%1,%2,%3}, {%4,%5,%6,%7}, {%8,%9}, {%0,%1,%2,%3};\n"              \
        : "+f"(d[0]), "+f"(d[1]), "+f"(d[2]), "+f"(d[3])                       \
        : "r"(a[0]), "r"(a[1]), "r"(a[2]), "r"(a[3]), "r"(b[0]), "r"(b[1]))

#define LDSM4(r, addr)                                                         \
    asm volatile("ldmatrix.sync.aligned.m8n8.x4.shared.b16 {%0,%1,%2,%3}, [%4];" \
        : "=r"((r)[0]), "=r"((r)[1]), "=r"((r)[2]), "=r"((r)[3]) : "r"(addr))

__device__ __forceinline__ void cp16(uint32_t dst, const void* src, int sz) {
    asm volatile("cp.async.cg.shared.global [%0], [%1], 16, %2;"
                 :: "r"(dst), "l"(src), "r"(sz));
}

__global__ __launch_bounds__(256, 2) void gemm_fp16_kernel(int M)
{
    __shared__ __half Ah[NSTAGE][BM][KPAD];
    __shared__ __half Bh[NSTAGE][BN][KPAD];

    const int tid = threadIdx.x;
    const int wid = tid >> 5;
    const int lane = tid & 31;
    const int g = lane >> 2;
    const int tg = lane & 3;
    const int wm = (wid & 3) * 32;
    const int wn = (wid >> 2) * 64;
    const int bm = blockIdx.x * BM;
    const int bn = blockIdx.y * BN;

    const int rsel = (lane & 7) + ((lane >> 3) & 1) * 8;  // 0..15
    const int csel = (lane >> 4) * 8;                     // 0 or 8

    const uint32_t aBase = (uint32_t)__cvta_generic_to_shared(&Ah[0][0][0]);
    const uint32_t bBase = (uint32_t)__cvta_generic_to_shared(&Bh[0][0][0]);
    const uint32_t stageA = (uint32_t)(BM * KPAD * sizeof(__half));
    const uint32_t stageB = (uint32_t)(BN * KPAD * sizeof(__half));

    float acc[2][8][4];
#pragma unroll
    for (int mi = 0; mi < 2; mi++)
#pragma unroll
        for (int ni = 0; ni < 8; ni++)
#pragma unroll
            for (int c = 0; c < 4; c++) acc[mi][ni][c] = 0.0f;

    // Tile fill: 128 rows x 4 uint4/row; each thread 2 uint4.
    const int arow = tid >> 1;
    const int au = (tid & 1) * 2;
    const bool ain = (bm + arow) < M;
    const int asz = ain ? 16 : 0;

    const __half* asrc = g_xh + (size_t)(bm + arow) * FEAT + au * 8;
    const __half* bsrc = g_wt + (size_t)(bn + arow) * FEAT + au * 8;
    const uint32_t arowoff = (uint32_t)((arow * KPAD + au * 8) * 2);

#define PREFETCH(kt, st)                                                       \
    do {                                                                       \
        uint32_t ad = aBase + (uint32_t)(st) * stageA + arowoff;               \
        uint32_t bd = bBase + (uint32_t)(st) * stageB + arowoff;               \
        int koff = (kt) * BK;                                                  \
        cp16(ad, asrc + koff, asz);                                            \
        cp16(ad + 16, asrc + koff + 8, asz);                                   \
        cp16(bd, bsrc + koff, 16);                                             \
        cp16(bd + 16, bsrc + koff + 8, 16);                                    \
        asm volatile("cp.async.commit_group;");                                \
    } while (0)

    // prologue: tiles 0 and 1
    PREFETCH(0, 0);
    PREFETCH(1, 1);

    const int NK = FEAT / BK;   // 8
    int cs = 0;                 // compute stage
    int ps = 2;                 // next prefetch stage
    for (int k0 = 0; k0 < NK; k0++) {
        if (k0 < NK - 1) {
            asm volatile("cp.async.wait_group 1;");
        } else {
            asm volatile("cp.async.wait_group 0;");
        }
        __syncthreads();   // stage cs ready; all warps done with stage cs's prior use

        if (k0 + 2 < NK) {
            PREFETCH(k0 + 2, ps);
            ps = (ps + 1 == NSTAGE) ? 0 : ps + 1;
        }

        uint32_t aS = aBase + (uint32_t)cs * stageA;
        uint32_t bS = bBase + (uint32_t)cs * stageB;
#pragma unroll
        for (int ksi = 0; ksi < 2; ksi++) {
            int ks = ksi * 16;
            uint32_t a[2][4];
#pragma unroll
            for (int mi = 0; mi < 2; mi++) {
                uint32_t addr = aS + (uint32_t)(((wm + mi * 16 + rsel) * KPAD + ks + csel) * 2);
                LDSM4(a[mi], addr);
            }
            uint32_t b[4][4];
#pragma unroll
            for (int pi = 0; pi < 4; pi++) {
                uint32_t addr = bS + (uint32_t)(((wn + pi * 16 + rsel) * KPAD + ks + csel) * 2);
                LDSM4(b[pi], addr);
            }
#pragma unroll
            for (int pi = 0; pi < 4; pi++) {
                uint32_t bb0[2] = {b[pi][0], b[pi][2]};
                uint32_t bb1[2] = {b[pi][1], b[pi][3]};
                MMA_FP16(acc[0][2 * pi],     a[0], bb0);
                MMA_FP16(acc[1][2 * pi],     a[1], bb0);
                MMA_FP16(acc[0][2 * pi + 1], a[0], bb1);
                MMA_FP16(acc[1][2 * pi + 1], a[1], bb1);
            }
        }
        cs = (cs + 1 == NSTAGE) ? 0 : cs + 1;
    }

    // epilogue: store y fp16 (unscaled)
    __half2* yh2 = (__half2*)g_yh;
#pragma unroll
    for (int mi = 0; mi < 2; mi++) {
        int r0 = bm + wm + mi * 16 + g;
        int r1 = r0 + 8;
#pragma unroll
        for (int ni = 0; ni < 8; ni++) {
            int c = bn + wn + ni * 8 + 2 * tg;
            if (r0 < M)
                yh2[(size_t)r0 * (FEAT / 2) + (c >> 1)] =
                    __floats2half2_rn(acc[mi][ni][0], acc[mi][ni][1]);
            if (r1 < M)
                yh2[(size_t)r1 * (FEAT / 2) + (c >> 1)] =
                    __floats2half2_rn(acc[mi][ni][2], acc[mi][ni][3]);
        }
    }
}

// ---------------------------------------------------------------------------
// Pull aggregation: one warp per dst node d.
// out[d] = relu(dinv[d] * (dinv[d]*y[d] + sum_s dinv[s]*y[s]) + b)
// ---------------------------------------------------------------------------
__device__ __forceinline__ void acc_row_w(float* acc, uint4 u, float w) {
    __half2* h = (__half2*)&u;
#pragma unroll
    for (int q = 0; q < 4; q++) {
        float2 f = __half22float2(h[q]);
        acc[2 * q]     = fmaf(f.x, w, acc[2 * q]);
        acc[2 * q + 1] = fmaf(f.y, w, acc[2 * q + 1]);
    }
}

__global__ __launch_bounds__(256) void pull_kernel(
    float* __restrict__ out, const float* __restrict__ bias, int N)
{
    int warp = (blockIdx.x * blockDim.x + threadIdx.x) >> 5;
    int lane = threadIdx.x & 31;
    if (warp >= N) return;

    int beg = g_off[warp];
    int end = g_off[warp + 1];
    float dv = g_dinv[warp];

    float acc[8] = {0.f, 0.f, 0.f, 0.f, 0.f, 0.f, 0.f, 0.f};
    {   // self loop, weight dinv[d]
        uint4 u = __ldg((const uint4*)(g_yh + (size_t)warp * FEAT) + lane);
        acc_row_w(acc, u, dv);
    }

    int j = beg;
    for (; j + 8 <= end; j += 8) {
        int s[8];
#pragma unroll
        for (int t = 0; t < 8; t++) s[t] = g_srcs[j + t];
        float w[8];
#pragma unroll
        for (int t = 0; t < 8; t++) w[t] = g_dinv[s[t]];
        uint4 u[8];
#pragma unroll
        for (int t = 0; t < 8; t++)
            u[t] = __ldg((const uint4*)(g_yh + (size_t)s[t] * FEAT) + lane);
#pragma unroll
        for (int t = 0; t < 8; t++) acc_row_w(acc, u[t], w[t]);
    }
    for (; j + 2 <= end; j += 2) {
        int s0 = g_srcs[j], s1 = g_srcs[j + 1];
        float w0 = g_dinv[s0], w1 = g_dinv[s1];
        uint4 u0 = __ldg((const uint4*)(g_yh + (size_t)s0 * FEAT) + lane);
        uint4 u1 = __ldg((const uint4*)(g_yh + (size_t)s1 * FEAT) + lane);
        acc_row_w(acc, u0, w0);
        acc_row_w(acc, u1, w1);
    }
    if (j < end) {
        int s0 = g_srcs[j];
        uint4 u0 = __ldg((const uint4*)(g_yh + (size_t)s0 * FEAT) + lane);
        acc_row_w(acc, u0, g_dinv[s0]);
    }

    float4 b0 = *(const float4*)(bias + lane * 8);
    float4 b1 = *(const float4*)(bias + lane * 8 + 4);
    float4 o0, o1;
    o0.x = fmaxf(fmaf(acc[0], dv, b0.x), 0.f);
    o0.y = fmaxf(fmaf(acc[1], dv, b0.y), 0.f);
    o0.z = fmaxf(fmaf(acc[2], dv, b0.z), 0.f);
    o0.w = fmaxf(fmaf(acc[3], dv, b0.w), 0.f);
    o1.x = fmaxf(fmaf(acc[4], dv, b1.x), 0.f);
    o1.y = fmaxf(fmaf(acc[5], dv, b1.y), 0.f);
    o1.z = fmaxf(fmaf(acc[6], dv, b1.z), 0.f);
    o1.w = fmaxf(fmaf(acc[7], dv, b1.w), 0.f);

    float* orow = out + (size_t)warp * FEAT + lane * 8;
    *(float4*)orow = o0;
    *(float4*)(orow + 4) = o1;
}

// ---------------------------------------------------------------------------
// Launch. GEMM at slot 3 (ncu -s 5 -c 1 lands there).
// ---------------------------------------------------------------------------
extern "C" void kernel_launch(void* const* d_in, const int* in_sizes, int n_in,
                              void* d_out, int out_size)
{
    const float* x = (const float*)d_in[0];
    const void*  e = d_in[1];
    const float* W = (const float*)d_in[2];
    const float* b = (const float*)d_in[3];
    float* out = (float*)d_out;

    const int N = in_sizes[0] / FEAT;   // 50000
    const int E = in_sizes[1] / 2;      // 1,600,000

    int total4 = N * (FEAT / 4);
    convert_x_kernel<<<(total4 + 255) / 256, 256>>>(x, total4);           // 0
    convert_w_init_kernel<<<FEAT * FEAT / 256, 256>>>(W, (const int*)e, N); // 1
    count_deg_kernel<<<(E + 255) / 256, 256>>>(e, E);                     // 2

    dim3 ggrid((N + BM - 1) / BM, FEAT / BN);
    gemm_fp16_kernel<<<ggrid, 256>>>(N);                                  // 3 (profiled)

    int NB = (N + SCB - 1) / SCB;
    block_sum_kernel<<<NB, SCB>>>(N);                                     // 4
    scan_bsum_kernel<<<1, 128>>>(NB);                                     // 5
    scan_final_kernel<<<NB, SCB>>>(N);                                    // 6
    fill_kernel<<<(E + 255) / 256, 256>>>(e, E);                          // 7

    int pblocks = (N + 7) / 8;
    pull_kernel<<<pblocks, 256>>>(out, b, N);                             // 8
}